// round 13
// baseline (speedup 1.0000x reference)
#include <cuda_runtime.h>
#include <cuda_fp16.h>
#include <cstdint>
#include <math.h>

#define BS   32768
#define NQ   8
#define FFN  2048
#define EMB  512

#define TMT  128              // tokens per CTA (GEMM)
#define TNT  128              // out cols per CTA
#define KC   64               // FFN chunk per iteration (4 x k16 steps)
#define NC   (FFN / KC)       // 32
#define NTH  128              // 4 warps, 2x2 grid of 64x64 warp tiles
#define ROWB 144              // A rows: 128B data + 16B pad (ldmatrix conflict-free)

#define NT16 (EMB / 16)       // 32 n16 tiles
#define KT16 (FFN / 16)       // 128 k16 steps

__device__ __half g_h[BS * FFN];
// B fragments: per (n16 tile j2, k16 step t, lane): uint4 = the 4 b32 ldmatrix
// x4 registers (matrices (n0-7,k0),(n0-7,k8),(n8-15,k0),(n8-15,k8)).
__device__ uint4 g_w2f[NT16 * KT16 * 32];

// ---- smem (GEMM): 2 stages x A 128x144 = 36 KB ----
#define SM_A(s)  ((s) * 18432)
#define SMEM_BYTES 36864

__device__ __forceinline__ uint32_t smem_u32(const void* p) {
    uint32_t a;
    asm("{ .reg .u64 t; cvta.to.shared.u64 t, %1; cvt.u32.u64 %0, t; }" : "=r"(a) : "l"(p));
    return a;
}

#define LDSM4(r, a)                                                            \
    asm volatile("ldmatrix.sync.aligned.m8n8.x4.shared.b16 {%0,%1,%2,%3}, [%4];" \
        : "=r"((r)[0]), "=r"((r)[1]), "=r"((r)[2]), "=r"((r)[3]) : "r"(a))

#define MMAF16(d, a, b0, b1v)                                                  \
    asm volatile("mma.sync.aligned.m16n8k16.row.col.f32.f16.f16.f32 "         \
        "{%0,%1,%2,%3},{%4,%5,%6,%7},{%8,%9},{%0,%1,%2,%3};"                  \
        : "+f"((d)[0]), "+f"((d)[1]), "+f"((d)[2]), "+f"((d)[3])              \
        : "r"((a)[0]), "r"((a)[1]), "r"((a)[2]), "r"((a)[3]), "r"(b0), "r"(b1v))

#define CP16(dst, src)                                                         \
    asm volatile("cp.async.cg.shared.global [%0], [%1], 16;" :: "r"(dst), "l"(src))
#define CP_COMMIT() asm volatile("cp.async.commit_group;" ::: "memory")
#define CP_WAIT1()  asm volatile("cp.async.wait_group 1;" ::: "memory")

// ---- prep: W2 [FFN][EMB] fp32 -> B fragments (via staging + ldmatrix) -----
// FIXED vs R12: each lane now writes 8 n-values (two float4 loads), so the
// full 16(n) x 16(k) tile (256 halves) is covered by the warp's 32 lanes:
//   kl = lane>>1 in [0,16) k-rows, n8 = (lane&1)*8 n-offset.
__global__ __launch_bounds__(128, 8)
void prep_frag_kernel(const float* __restrict__ W2)
{
    __shared__ __align__(16) char stage[4][16 * 48];   // per-warp: 16 n-rows x 48B
    const int tid  = threadIdx.x;
    const int wid  = tid >> 5;
    const int lane = tid & 31;
    const int j2    = blockIdx.x >> 3;            // n16 tile
    const int tbase = (blockIdx.x & 7) * 16;
    const uint32_t sb = smem_u32(&stage[wid][0]);
    // same intra-tile lane->address pattern as the verified gemm b_off (ROWB=48)
    const uint32_t lb = sb + (uint32_t)((lane & 7) + ((lane & 16) >> 1)) * 48
                      + ((lane & 8) << 1);

    const int kl = lane >> 1;                     // k within tile, 0..15
    const int n8 = (lane & 1) * 8;                // n-half within tile: 0 or 8

    for (int i = 0; i < 4; i++) {
        const int t = tbase + wid * 4 + i;
        // load W2[k = t*16 + kl][n = j2*16 + n8 .. n8+7] (fp32), convert, stage
        const float* wrow = &W2[(size_t)(t * 16 + kl) * EMB + j2 * 16 + n8];
        float4 v0 = *(const float4*)(wrow);
        float4 v1 = *(const float4*)(wrow + 4);
        char* base = &stage[wid][0] + kl * 2;     // k stride 2B within an n-row
        *(__half*)(base + (n8 + 0) * 48) = __float2half_rn(v0.x);
        *(__half*)(base + (n8 + 1) * 48) = __float2half_rn(v0.y);
        *(__half*)(base + (n8 + 2) * 48) = __float2half_rn(v0.z);
        *(__half*)(base + (n8 + 3) * 48) = __float2half_rn(v0.w);
        *(__half*)(base + (n8 + 4) * 48) = __float2half_rn(v1.x);
        *(__half*)(base + (n8 + 5) * 48) = __float2half_rn(v1.y);
        *(__half*)(base + (n8 + 6) * 48) = __float2half_rn(v1.z);
        *(__half*)(base + (n8 + 7) * 48) = __float2half_rn(v1.w);
        __syncwarp();
        uint32_t bh[4];
        LDSM4(bh, lb);
        g_w2f[((size_t)j2 * KT16 + t) * 32 + lane] = make_uint4(bh[0], bh[1], bh[2], bh[3]);
        __syncwarp();
    }
}

// ---- kernel 1: H = fp16(relu(q @ W1 + b1)) (R8-exact) ----------------------
#define TB 64
__global__ __launch_bounds__(256, 2)
void h_kernel(const float* __restrict__ x,
              const float* __restrict__ theta,
              const float* __restrict__ W1,
              const float* __restrict__ b1)
{
    __shared__ float q_s[TB][NQ];
    const int tid  = threadIdx.x;
    const int row0 = blockIdx.x * TB;
    const int k0   = tid * 8;

    #pragma unroll
    for (int i = tid; i < TB * NQ; i += 256) {
        int m = i >> 3, j = i & 7;
        q_s[m][j] = cosf(x[(size_t)(row0 + m) * NQ + j]) * cosf(__ldg(&theta[j]));
    }

    float w1r[8][NQ];
    float b1r[8];
    #pragma unroll
    for (int u = 0; u < 8; u++) {
        b1r[u] = __ldg(&b1[k0 + u]);
        #pragma unroll
        for (int j = 0; j < NQ; j++)
            w1r[u][j] = __ldg(&W1[(size_t)j * FFN + k0 + u]);
    }
    __syncthreads();

    for (int t = 0; t < TB; t++) {
        float4 qa = *(const float4*)&q_s[t][0];
        float4 qb = *(const float4*)&q_s[t][4];
        uint32_t w[4];
        #pragma unroll
        for (int u = 0; u < 8; u++) {
            float s = b1r[u];
            s = fmaf(qa.x, w1r[u][0], s); s = fmaf(qa.y, w1r[u][1], s);
            s = fmaf(qa.z, w1r[u][2], s); s = fmaf(qa.w, w1r[u][3], s);
            s = fmaf(qb.x, w1r[u][4], s); s = fmaf(qb.y, w1r[u][5], s);
            s = fmaf(qb.z, w1r[u][6], s); s = fmaf(qb.w, w1r[u][7], s);
            s = fmaxf(s, 0.f);
            uint32_t hb = (uint32_t)__half_as_ushort(__float2half_rn(s));
            if (u & 1) w[u >> 1] |= hb << 16;
            else       w[u >> 1]  = hb;
        }
        *(uint4*)((char*)(g_h + (size_t)(row0 + t) * FFN) + tid * 16)
            = make_uint4(w[0], w[1], w[2], w[3]);
    }
}

// ---- gemm: A via cp.async+LDSM, B via direct LDG.128 of fragments ----------
__global__ __launch_bounds__(NTH, 2)
void gemm_kernel(const float* __restrict__ b2, float* __restrict__ out)
{
    extern __shared__ char sm[];
    const uint32_t smb = smem_u32(sm);

    const int tid  = threadIdx.x;
    const int wid  = tid >> 5;
    const int lane = tid & 31;
    const int col0 = blockIdx.x * TNT;      // x fastest: 4 col CTAs share A via L2
    const int row0 = blockIdx.y * TMT;
    const int wm   = wid & 1;               // 2 M groups of 64 rows
    const int wn   = wid >> 1;              // 2 N groups of 64 cols

    const uint32_t a_off = (uint32_t)(wm * 64 + (lane & 15)) * ROWB + ((lane >> 4) << 4);

    // B fragment base for this warp: n16 tiles jb..jb+3 (g), lane-indexed
    const int jb = (col0 >> 4) + wn * 4;
    const uint4* gBf = g_w2f + ((size_t)jb * KT16) * 32 + lane;
    // index for (g, t): g*KT16*32 + t*32

    // cp.async A: thread covers row = (tid>>3) + 16*r, 16B segment = tid&7
    const int ldr = tid >> 3;
    const int seg = (tid & 7) * 16;
    const char* gA = (const char*)(g_h + (size_t)(row0 + ldr) * FFN) + seg;
    const uint32_t soA = (uint32_t)ldr * ROWB + seg;

    auto issueA = [&](int chunk, int s) {
        const char* a = gA + chunk * (KC * 2);
        #pragma unroll
        for (int r = 0; r < 8; r++)
            CP16(smb + SM_A(s) + soA + r * 16 * ROWB, a + (size_t)r * 16 * FFN * 2);
    };

    float acc[4][8][4];
    #pragma unroll
    for (int a = 0; a < 4; a++)
        #pragma unroll
        for (int b = 0; b < 8; b++)
            #pragma unroll
            for (int i = 0; i < 4; i++) acc[a][b][i] = 0.f;

    issueA(0, 0);
    CP_COMMIT();

    for (int c = 0; c < NC; c++) {
        const int s = c & 1;
        const int t0 = c * 4;

        if (c + 1 < NC) issueA(c + 1, s ^ 1);
        CP_COMMIT();

        // B fragments for ks=0 (gmem/L2) — issued before the smem wait
        uint4 bfr[2][4];
        #pragma unroll
        for (int g = 0; g < 4; g++)
            bfr[0][g] = __ldg(gBf + (size_t)g * KT16 * 32 + t0 * 32);

        CP_WAIT1();             // A chunk c landed; c+1 in flight
        __syncthreads();

        const uint32_t A = smb + SM_A(s) + a_off;
        #pragma unroll
        for (int ks = 0; ks < 4; ks++) {
            const int cur = ks & 1;
            if (ks < 3) {
                #pragma unroll
                for (int g = 0; g < 4; g++)
                    bfr[cur ^ 1][g] = __ldg(gBf + (size_t)g * KT16 * 32 + (t0 + ks + 1) * 32);
            }
            uint32_t ah[4][4];
            #pragma unroll
            for (int mt = 0; mt < 4; mt++)
                LDSM4(ah[mt], A + mt * 16 * ROWB + ks * 32);
            #pragma unroll
            for (int g = 0; g < 4; g++) {
                #pragma unroll
                for (int mt = 0; mt < 4; mt++) {
                    MMAF16(acc[mt][2 * g],     ah[mt], bfr[cur][g].x, bfr[cur][g].y);
                    MMAF16(acc[mt][2 * g + 1], ah[mt], bfr[cur][g].z, bfr[cur][g].w);
                }
            }
        }
        __syncthreads();        // stage s free for prefetch next iter
    }

    // epilogue: D frags + b2
    #pragma unroll
    for (int mt = 0; mt < 4; mt++) {
        int mrow = row0 + wm * 64 + mt * 16 + (lane >> 2);
        #pragma unroll
        for (int nt = 0; nt < 8; nt++) {
            int ncol = col0 + wn * 64 + nt * 8 + (lane & 3) * 2;
            float bx = b2[ncol], by = b2[ncol + 1];
            float2 v0 = make_float2(acc[mt][nt][0] + bx, acc[mt][nt][1] + by);
            float2 v1 = make_float2(acc[mt][nt][2] + bx, acc[mt][nt][3] + by);
            *(float2*)&out[(size_t)mrow * EMB + ncol]       = v0;
            *(float2*)&out[(size_t)(mrow + 8) * EMB + ncol] = v1;
        }
    }
}

// ---- launcher ----------------------------------------------------------------
extern "C" void kernel_launch(void* const* d_in, const int* in_sizes, int n_in,
                              void* d_out, int out_size)
{
    const float *x = 0, *theta = 0, *W1 = 0, *b1 = 0, *W2 = 0, *b2 = 0;
    for (int i = 0; i < n_in; i++) {
        switch (in_sizes[i]) {
            case BS * NQ:   x     = (const float*)d_in[i]; break;
            case NQ:        theta = (const float*)d_in[i]; break;
            case NQ * FFN:  W1    = (const float*)d_in[i]; break;
            case FFN:       b1    = (const float*)d_in[i]; break;
            case FFN * EMB: W2    = (const float*)d_in[i]; break;
            case EMB:       b2    = (const float*)d_in[i]; break;
            default: break;
        }
    }

    prep_frag_kernel<<<NT16 * 8, 128>>>(W2);   // 256 blocks
    h_kernel<<<BS / TB, 256>>>(x, theta, W1, b1);

    cudaFuncSetAttribute(gemm_kernel, cudaFuncAttributeMaxDynamicSharedMemorySize,
                         SMEM_BYTES);
    dim3 grid(EMB / TNT, BS / TMT);   // 4 x 256; col-fastest for L2 A reuse
    gemm_kernel<<<grid, NTH, SMEM_BYTES>>>(b2, (float*)d_out);
}

// round 14
// speedup vs baseline: 1.1471x; 1.1471x over previous
#include <cuda_runtime.h>
#include <cuda_fp16.h>
#include <cstdint>
#include <math.h>

#define BS   32768
#define NQ   8
#define FFN  2048
#define EMB  512

#define TMT  128              // tokens per CTA (GEMM)
#define TNT  64               // out cols per CTA
#define KC   64               // FFN chunk per iteration
#define NC   (FFN / KC)       // 32
#define NTH  128              // 4 warps: 2x2 grid of 64x32 warp tiles
#define ROWB 144              // 128B data + 16B pad -> ldmatrix conflict-free

__device__ __half g_h[BS * FFN];
__device__ __half g_w2t[EMB * FFN];

// ---- smem (GEMM): 2 stages x (A 128x144 + B 64x144) = 54 KB -> 4 CTAs/SM ----
#define SM_A(s)  ((s) * 27648)
#define SM_B(s)  ((s) * 27648 + 18432)
#define SMEM_BYTES 55296

__device__ __forceinline__ uint32_t smem_u32(const void* p) {
    uint32_t a;
    asm("{ .reg .u64 t; cvta.to.shared.u64 t, %1; cvt.u32.u64 %0, t; }" : "=r"(a) : "l"(p));
    return a;
}

#define LDSM4(r, a)                                                            \
    asm volatile("ldmatrix.sync.aligned.m8n8.x4.shared.b16 {%0,%1,%2,%3}, [%4];" \
        : "=r"((r)[0]), "=r"((r)[1]), "=r"((r)[2]), "=r"((r)[3]) : "r"(a))

#define MMAF16(d, a, b0, b1v)                                                  \
    asm volatile("mma.sync.aligned.m16n8k16.row.col.f32.f16.f16.f32 "         \
        "{%0,%1,%2,%3},{%4,%5,%6,%7},{%8,%9},{%0,%1,%2,%3};"                  \
        : "+f"((d)[0]), "+f"((d)[1]), "+f"((d)[2]), "+f"((d)[3])              \
        : "r"((a)[0]), "r"((a)[1]), "r"((a)[2]), "r"((a)[3]), "r"(b0), "r"(b1v))

#define CP16(dst, src)                                                         \
    asm volatile("cp.async.cg.shared.global [%0], [%1], 16;" :: "r"(dst), "l"(src))
#define CP_COMMIT() asm volatile("cp.async.commit_group;" ::: "memory")
#define CP_WAIT1()  asm volatile("cp.async.wait_group 1;" ::: "memory")

// ---- pre kernel: h (blocks [0,512)) + W2 transpose (blocks [512, 4608)) ----
// h part: H = fp16(relu(q @ W1 + b1)) computed with HFMA2; W1/b1 converted to
// half2 in-register (no cross-block dependency). Two 4-deep accumulation
// chains bound fp16 rounding depth.
#define TB 64
#define HBLKS (BS / TB)            // 512
__global__ __launch_bounds__(256, 2)
void pre_kernel(const float* __restrict__ x,
                const float* __restrict__ theta,
                const float* __restrict__ W1,
                const float* __restrict__ b1,
                const float* __restrict__ W2)
{
    const int tid = threadIdx.x;

    if (blockIdx.x >= HBLKS) {
        // ---- W2T: g_w2t[n][k] = fp16(W2[k][n]) ----
        int t = (blockIdx.x - HBLKS) * 256 + tid;
        int n = t >> 11;
        int k = t & (FFN - 1);
        g_w2t[t] = __float2half_rn(W2[(size_t)k * EMB + n]);
        return;
    }

    // ---- h part ----
    __shared__ __half2 q2_s[TB][NQ];
    const int row0 = blockIdx.x * TB;
    const int k0   = tid * 8;               // this thread's 8 FFN columns

    #pragma unroll
    for (int i = tid; i < TB * NQ; i += 256) {
        int m = i >> 3, j = i & 7;
        float qv = cosf(x[(size_t)(row0 + m) * NQ + j]) * cosf(__ldg(&theta[j]));
        q2_s[m][j] = __half2half2(__float2half_rn(qv));
    }

    // W1 slice [8 j][4 half2-pairs] + b1 slice, converted to half2 in regs
    __half2 w1h[8][4];
    __half2 b1h[4];
    #pragma unroll
    for (int j = 0; j < NQ; j++) {
        float4 a = *(const float4*)&W1[(size_t)j * FFN + k0];
        float4 b = *(const float4*)&W1[(size_t)j * FFN + k0 + 4];
        w1h[j][0] = __floats2half2_rn(a.x, a.y);
        w1h[j][1] = __floats2half2_rn(a.z, a.w);
        w1h[j][2] = __floats2half2_rn(b.x, b.y);
        w1h[j][3] = __floats2half2_rn(b.z, b.w);
    }
    {
        float4 a = *(const float4*)&b1[k0];
        float4 b = *(const float4*)&b1[k0 + 4];
        b1h[0] = __floats2half2_rn(a.x, a.y);
        b1h[1] = __floats2half2_rn(a.z, a.w);
        b1h[2] = __floats2half2_rn(b.x, b.y);
        b1h[3] = __floats2half2_rn(b.z, b.w);
    }
    __syncthreads();

    const __half2 zero2 = __float2half2_rn(0.f);
    for (int t = 0; t < TB; t++) {
        __half2 q2[NQ];
        #pragma unroll
        for (int j = 0; j < NQ; j++) q2[j] = q2_s[t][j];

        __half2 acc[4], accb[4];
        #pragma unroll
        for (int p = 0; p < 4; p++) {
            acc[p]  = __hfma2(q2[0], w1h[0][p], b1h[p]);
            accb[p] = __hmul2(q2[4], w1h[4][p]);
        }
        #pragma unroll
        for (int j = 1; j < 4; j++)
            #pragma unroll
            for (int p = 0; p < 4; p++) {
                acc[p]  = __hfma2(q2[j],     w1h[j][p],     acc[p]);
                accb[p] = __hfma2(q2[j + 4], w1h[j + 4][p], accb[p]);
            }

        uint32_t w[4];
        #pragma unroll
        for (int p = 0; p < 4; p++) {
            __half2 r = __hmax2(__hadd2(acc[p], accb[p]), zero2);
            w[p] = *(uint32_t*)&r;
        }
        *(uint4*)((char*)(g_h + (size_t)(row0 + t) * FFN) + tid * 16)
            = make_uint4(w[0], w[1], w[2], w[3]);
    }
}

// ---- gemm: out = H @ W2 + b2; 128x64 CTA, 4 CTAs/SM (R11 verbatim) ---------
__global__ __launch_bounds__(NTH, 4)
void gemm_kernel(const float* __restrict__ b2, float* __restrict__ out)
{
    extern __shared__ char sm[];
    const uint32_t smb = smem_u32(sm);

    const int tid  = threadIdx.x;
    const int wid  = tid >> 5;
    const int lane = tid & 31;
    const int col0 = blockIdx.x * TNT;      // x fastest: 8 col CTAs share A via L2
    const int row0 = blockIdx.y * TMT;
    const int wm   = wid & 1;               // 2 M groups of 64 rows
    const int wn   = wid >> 1;              // 2 N groups of 32 cols

    const uint32_t a_off = (uint32_t)(wm * 64 + (lane & 15)) * ROWB + ((lane >> 4) << 4);
    const uint32_t b_off = (uint32_t)(wn * 32 + (lane & 7) + ((lane & 16) >> 1)) * ROWB
                         + ((lane & 8) << 1);

    // cp.async: thread covers row = (tid>>3) + 16*r, 16B segment = tid&7
    const int ldr = tid >> 3;
    const int seg = (tid & 7) * 16;
    const char* gA = (const char*)(g_h   + (size_t)(row0 + ldr) * FFN) + seg;
    const char* gB = (const char*)(g_w2t + (size_t)(col0 + ldr) * FFN) + seg;
    const uint32_t soA = (uint32_t)ldr * ROWB + seg;

    auto issue = [&](int chunk, int s) {
        const char* a = gA + chunk * (KC * 2);
        const char* b = gB + chunk * (KC * 2);
        #pragma unroll
        for (int r = 0; r < 8; r++)         // A: 128 rows
            CP16(smb + SM_A(s) + soA + r * 16 * ROWB, a + (size_t)r * 16 * FFN * 2);
        #pragma unroll
        for (int r = 0; r < 4; r++)         // B: 64 rows
            CP16(smb + SM_B(s) + soA + r * 16 * ROWB, b + (size_t)r * 16 * FFN * 2);
    };

    float acc[4][4][4];
    #pragma unroll
    for (int a = 0; a < 4; a++)
        #pragma unroll
        for (int b = 0; b < 4; b++)
            #pragma unroll
            for (int i = 0; i < 4; i++) acc[a][b][i] = 0.f;

    issue(0, 0);
    CP_COMMIT();

    for (int c = 0; c < NC; c++) {
        const int s = c & 1;

        if (c + 1 < NC) issue(c + 1, s ^ 1);
        CP_COMMIT();
        CP_WAIT1();             // chunk c landed; c+1 may stay in flight
        __syncthreads();

        const uint32_t A = smb + SM_A(s) + a_off;
        const uint32_t B = smb + SM_B(s) + b_off;
        #pragma unroll
        for (int ks = 0; ks < 4; ks++) {
            uint32_t ah[4][4];
            #pragma unroll
            for (int mt = 0; mt < 4; mt++)
                LDSM4(ah[mt], A + mt * 16 * ROWB + ks * 32);
            #pragma unroll
            for (int g = 0; g < 2; g++) {
                uint32_t bh[4];
                LDSM4(bh, B + g * 16 * ROWB + ks * 32);
                #pragma unroll
                for (int mt = 0; mt < 4; mt++) {
                    MMAF16(acc[mt][2 * g],     ah[mt], bh[0], bh[1]);
                    MMAF16(acc[mt][2 * g + 1], ah[mt], bh[2], bh[3]);
                }
            }
        }
        __syncthreads();        // stage s free for prefetch next iter
    }

    // epilogue: D frags + b2
    #pragma unroll
    for (int mt = 0; mt < 4; mt++) {
        int mrow = row0 + wm * 64 + mt * 16 + (lane >> 2);
        #pragma unroll
        for (int nt = 0; nt < 4; nt++) {
            int ncol = col0 + wn * 32 + nt * 8 + (lane & 3) * 2;
            float bx = b2[ncol], by = b2[ncol + 1];
            float2 v0 = make_float2(acc[mt][nt][0] + bx, acc[mt][nt][1] + by);
            float2 v1 = make_float2(acc[mt][nt][2] + bx, acc[mt][nt][3] + by);
            *(float2*)&out[(size_t)mrow * EMB + ncol]       = v0;
            *(float2*)&out[(size_t)(mrow + 8) * EMB + ncol] = v1;
        }
    }
}

// ---- launcher ----------------------------------------------------------------
extern "C" void kernel_launch(void* const* d_in, const int* in_sizes, int n_in,
                              void* d_out, int out_size)
{
    const float *x = 0, *theta = 0, *W1 = 0, *b1 = 0, *W2 = 0, *b2 = 0;
    for (int i = 0; i < n_in; i++) {
        switch (in_sizes[i]) {
            case BS * NQ:   x     = (const float*)d_in[i]; break;
            case NQ:        theta = (const float*)d_in[i]; break;
            case NQ * FFN:  W1    = (const float*)d_in[i]; break;
            case FFN:       b1    = (const float*)d_in[i]; break;
            case FFN * EMB: W2    = (const float*)d_in[i]; break;
            case EMB:       b2    = (const float*)d_in[i]; break;
            default: break;
        }
    }

    pre_kernel<<<HBLKS + (EMB * FFN / 256), 256>>>(x, theta, W1, b1, W2);

    cudaFuncSetAttribute(gemm_kernel, cudaFuncAttributeMaxDynamicSharedMemorySize,
                         SMEM_BYTES);
    dim3 grid(EMB / TNT, BS / TMT);   // 8 x 256; col-fastest for L2 A reuse
    gemm_kernel<<<grid, NTH, SMEM_BYTES>>>(b2, (float*)d_out);
}

// round 16
// speedup vs baseline: 1.1699x; 1.0199x over previous
#include <cuda_runtime.h>
#include <cuda_fp16.h>
#include <cstdint>
#include <math.h>

#define BS   32768
#define NQ   8
#define FFN  2048
#define EMB  512

#define TMT  128              // tokens per CTA (GEMM)
#define TNT  64               // out cols per CTA
#define KC   64               // FFN chunk per iteration
#define NC   (FFN / KC)       // 32
#define NTH  128              // 4 warps: 2x2 grid of 64x32 warp tiles
#define ROWB 144              // 128B data + 16B pad -> ldmatrix conflict-free

__device__ __half g_h[BS * FFN];
__device__ __half g_w2t[EMB * FFN];

// ---- smem (GEMM): 2 stages x (A 128x144 + B 64x144) = 54 KB -> 4 CTAs/SM ----
#define SM_A(s)  ((s) * 27648)
#define SM_B(s)  ((s) * 27648 + 18432)
#define SMEM_BYTES 55296

__device__ __forceinline__ uint32_t smem_u32(const void* p) {
    uint32_t a;
    asm("{ .reg .u64 t; cvta.to.shared.u64 t, %1; cvt.u32.u64 %0, t; }" : "=r"(a) : "l"(p));
    return a;
}

#define LDSM4(r, a)                                                            \
    asm volatile("ldmatrix.sync.aligned.m8n8.x4.shared.b16 {%0,%1,%2,%3}, [%4];" \
        : "=r"((r)[0]), "=r"((r)[1]), "=r"((r)[2]), "=r"((r)[3]) : "r"(a))

#define MMAF16(d, a, b0, b1v)                                                  \
    asm volatile("mma.sync.aligned.m16n8k16.row.col.f32.f16.f16.f32 "         \
        "{%0,%1,%2,%3},{%4,%5,%6,%7},{%8,%9},{%0,%1,%2,%3};"                  \
        : "+f"((d)[0]), "+f"((d)[1]), "+f"((d)[2]), "+f"((d)[3])              \
        : "r"((a)[0]), "r"((a)[1]), "r"((a)[2]), "r"((a)[3]), "r"(b0), "r"(b1v))

#define CP16(dst, src)                                                         \
    asm volatile("cp.async.cg.shared.global [%0], [%1], 16;" :: "r"(dst), "l"(src))
#define CP_COMMIT() asm volatile("cp.async.commit_group;" ::: "memory")
#define CP_WAIT1()  asm volatile("cp.async.wait_group 1;" ::: "memory")

// ---- pre kernel ------------------------------------------------------------
// blocks [0, HBLKS):        H = fp16(relu(q @ W1 + b1)) via HFMA2 (R14-exact)
// blocks [HBLKS, +1024):    W2T coalesced 32x32 smem-tiled transpose+convert
#define TB 64
#define HBLKS (BS / TB)            // 512
#define W2T_BLKS ((EMB / 32) * (FFN / 32))   // 16 * 64 = 1024
__global__ __launch_bounds__(256, 2)
void pre_kernel(const float* __restrict__ x,
                const float* __restrict__ theta,
                const float* __restrict__ W1,
                const float* __restrict__ b1,
                const float* __restrict__ W2)
{
    const int tid = threadIdx.x;

    if (blockIdx.x >= HBLKS) {
        // ---- W2T tile: read W2[k0+r][n0..n0+31] coalesced, write
        //      g_w2t[n0+wr][k0..k0+31] coalesced ----
        // Row stride 36 halves = 72 B: even -> 4B-aligned uint32 reads.
        __shared__ __half stile[32][36];
        const int b  = blockIdx.x - HBLKS;
        const int n0 = (b & 15) * 32;              // 16 n-tiles
        const int k0 = (b >> 4) * 32;              // 64 k-tiles

        {   // read phase: thread covers (r = tid>>3, c4 = (tid&7)*4)
            const int r  = tid >> 3;
            const int c4 = (tid & 7) * 4;
            float4 v = *(const float4*)&W2[(size_t)(k0 + r) * EMB + n0 + c4];
            stile[c4 + 0][r] = __float2half_rn(v.x);
            stile[c4 + 1][r] = __float2half_rn(v.y);
            stile[c4 + 2][r] = __float2half_rn(v.z);
            stile[c4 + 3][r] = __float2half_rn(v.w);
        }
        __syncthreads();
        {   // write phase: thread covers (wr = tid>>3, wc = (tid&7)*4), 8B
            const int wr = tid >> 3;
            const int wc = (tid & 7) * 4;
            uint2 o;
            o.x = *(const uint32_t*)&stile[wr][wc];
            o.y = *(const uint32_t*)&stile[wr][wc + 2];
            *(uint2*)&g_w2t[(size_t)(n0 + wr) * FFN + k0 + wc] = o;
        }
        return;
    }

    // ---- h part (R14-exact) ----
    __shared__ __half2 q2_s[TB][NQ];
    const int row0 = blockIdx.x * TB;
    const int k0   = tid * 8;

    #pragma unroll
    for (int i = tid; i < TB * NQ; i += 256) {
        int m = i >> 3, j = i & 7;
        float qv = cosf(x[(size_t)(row0 + m) * NQ + j]) * cosf(__ldg(&theta[j]));
        q2_s[m][j] = __half2half2(__float2half_rn(qv));
    }

    __half2 w1h[8][4];
    __half2 b1h[4];
    #pragma unroll
    for (int j = 0; j < NQ; j++) {
        float4 a = *(const float4*)&W1[(size_t)j * FFN + k0];
        float4 b = *(const float4*)&W1[(size_t)j * FFN + k0 + 4];
        w1h[j][0] = __floats2half2_rn(a.x, a.y);
        w1h[j][1] = __floats2half2_rn(a.z, a.w);
        w1h[j][2] = __floats2half2_rn(b.x, b.y);
        w1h[j][3] = __floats2half2_rn(b.z, b.w);
    }
    {
        float4 a = *(const float4*)&b1[k0];
        float4 b = *(const float4*)&b1[k0 + 4];
        b1h[0] = __floats2half2_rn(a.x, a.y);
        b1h[1] = __floats2half2_rn(a.z, a.w);
        b1h[2] = __floats2half2_rn(b.x, b.y);
        b1h[3] = __floats2half2_rn(b.z, b.w);
    }
    __syncthreads();

    const __half2 zero2 = __float2half2_rn(0.f);
    for (int t = 0; t < TB; t++) {
        __half2 q2[NQ];
        #pragma unroll
        for (int j = 0; j < NQ; j++) q2[j] = q2_s[t][j];

        __half2 acc[4], accb[4];
        #pragma unroll
        for (int p = 0; p < 4; p++) {
            acc[p]  = __hfma2(q2[0], w1h[0][p], b1h[p]);
            accb[p] = __hmul2(q2[4], w1h[4][p]);
        }
        #pragma unroll
        for (int j = 1; j < 4; j++)
            #pragma unroll
            for (int p = 0; p < 4; p++) {
                acc[p]  = __hfma2(q2[j],     w1h[j][p],     acc[p]);
                accb[p] = __hfma2(q2[j + 4], w1h[j + 4][p], accb[p]);
            }

        uint32_t w[4];
        #pragma unroll
        for (int p = 0; p < 4; p++) {
            __half2 r = __hmax2(__hadd2(acc[p], accb[p]), zero2);
            w[p] = *(uint32_t*)&r;
        }
        *(uint4*)((char*)(g_h + (size_t)(row0 + t) * FFN) + tid * 16)
            = make_uint4(w[0], w[1], w[2], w[3]);
    }
}

// ---- gemm: out = H @ W2 + b2; 128x64 CTA, 4 CTAs/SM (R14-exact) ------------
__global__ __launch_bounds__(NTH, 4)
void gemm_kernel(const float* __restrict__ b2, float* __restrict__ out)
{
    extern __shared__ char sm[];
    const uint32_t smb = smem_u32(sm);

    const int tid  = threadIdx.x;
    const int wid  = tid >> 5;
    const int lane = tid & 31;
    const int col0 = blockIdx.x * TNT;      // x fastest: 8 col CTAs share A via L2
    const int row0 = blockIdx.y * TMT;
    const int wm   = wid & 1;               // 2 M groups of 64 rows
    const int wn   = wid >> 1;              // 2 N groups of 32 cols

    const uint32_t a_off = (uint32_t)(wm * 64 + (lane & 15)) * ROWB + ((lane >> 4) << 4);
    const uint32_t b_off = (uint32_t)(wn * 32 + (lane & 7) + ((lane & 16) >> 1)) * ROWB
                         + ((lane & 8) << 1);

    const int ldr = tid >> 3;
    const int seg = (tid & 7) * 16;
    const char* gA = (const char*)(g_h   + (size_t)(row0 + ldr) * FFN) + seg;
    const char* gB = (const char*)(g_w2t + (size_t)(col0 + ldr) * FFN) + seg;
    const uint32_t soA = (uint32_t)ldr * ROWB + seg;

    auto issue = [&](int chunk, int s) {
        const char* a = gA + chunk * (KC * 2);
        const char* b = gB + chunk * (KC * 2);
        #pragma unroll
        for (int r = 0; r < 8; r++)
            CP16(smb + SM_A(s) + soA + r * 16 * ROWB, a + (size_t)r * 16 * FFN * 2);
        #pragma unroll
        for (int r = 0; r < 4; r++)
            CP16(smb + SM_B(s) + soA + r * 16 * ROWB, b + (size_t)r * 16 * FFN * 2);
    };

    float acc[4][4][4];
    #pragma unroll
    for (int a = 0; a < 4; a++)
        #pragma unroll
        for (int b = 0; b < 4; b++)
            #pragma unroll
            for (int i = 0; i < 4; i++) acc[a][b][i] = 0.f;

    issue(0, 0);
    CP_COMMIT();

    for (int c = 0; c < NC; c++) {
        const int s = c & 1;

        if (c + 1 < NC) issue(c + 1, s ^ 1);
        CP_COMMIT();
        CP_WAIT1();
        __syncthreads();

        const uint32_t A = smb + SM_A(s) + a_off;
        const uint32_t B = smb + SM_B(s) + b_off;
        #pragma unroll
        for (int ks = 0; ks < 4; ks++) {
            uint32_t ah[4][4];
            #pragma unroll
            for (int mt = 0; mt < 4; mt++)
                LDSM4(ah[mt], A + mt * 16 * ROWB + ks * 32);
            #pragma unroll
            for (int g = 0; g < 2; g++) {
                uint32_t bh[4];
                LDSM4(bh, B + g * 16 * ROWB + ks * 32);
                #pragma unroll
                for (int mt = 0; mt < 4; mt++) {
                    MMAF16(acc[mt][2 * g],     ah[mt], bh[0], bh[1]);
                    MMAF16(acc[mt][2 * g + 1], ah[mt], bh[2], bh[3]);
                }
            }
        }
        __syncthreads();
    }

    #pragma unroll
    for (int mt = 0; mt < 4; mt++) {
        int mrow = row0 + wm * 64 + mt * 16 + (lane >> 2);
        #pragma unroll
        for (int nt = 0; nt < 4; nt++) {
            int ncol = col0 + wn * 32 + nt * 8 + (lane & 3) * 2;
            float bx = b2[ncol], by = b2[ncol + 1];
            float2 v0 = make_float2(acc[mt][nt][0] + bx, acc[mt][nt][1] + by);
            float2 v1 = make_float2(acc[mt][nt][2] + bx, acc[mt][nt][3] + by);
            *(float2*)&out[(size_t)mrow * EMB + ncol]       = v0;
            *(float2*)&out[(size_t)(mrow + 8) * EMB + ncol] = v1;
        }
    }
}

// ---- launcher ----------------------------------------------------------------
extern "C" void kernel_launch(void* const* d_in, const int* in_sizes, int n_in,
                              void* d_out, int out_size)
{
    const float *x = 0, *theta = 0, *W1 = 0, *b1 = 0, *W2 = 0, *b2 = 0;
    for (int i = 0; i < n_in; i++) {
        switch (in_sizes[i]) {
            case BS * NQ:   x     = (const float*)d_in[i]; break;
            case NQ:        theta = (const float*)d_in[i]; break;
            case NQ * FFN:  W1    = (const float*)d_in[i]; break;
            case FFN:       b1    = (const float*)d_in[i]; break;
            case FFN * EMB: W2    = (const float*)d_in[i]; break;
            case EMB:       b2    = (const float*)d_in[i]; break;
            default: break;
        }
    }

    pre_kernel<<<HBLKS + W2T_BLKS, 256>>>(x, theta, W1, b1, W2);

    cudaFuncSetAttribute(gemm_kernel, cudaFuncAttributeMaxDynamicSharedMemorySize,
                         SMEM_BYTES);
    dim3 grid(EMB / TNT, BS / TMT);   // 8 x 256; col-fastest for L2 A reuse
    gemm_kernel<<<grid, NTH, SMEM_BYTES>>>(b2, (float*)d_out);
}